// round 11
// baseline (speedup 1.0000x reference)
#include <cuda_runtime.h>

#define BB   64
#define HH   384
#define NPLT 16
#define NG   25
#define CAND 625   // NG*NG
#define LF   400   // HH + NPLT
#define NP   4     // internal j-passes in S phase
#define JCH  96    // j per pass (4*96 = 384)
#define TROW 28    // padded table row (floats): 7 tiles x 4, 112B rows

#define LOG2E_F  1.4426950408889634f
#define LOG2PI_F 1.8378770664093453f

// persistent scratch (allocation-free rule: __device__ globals)
__device__ float g_arg[BB];      // argmin-block loglik partial (plain store)
__device__ float g_tri[BB][2];   // triangle partials (plain store)

__device__ __forceinline__ float ex2f(float x) {
    float r;
    asm("ex2.approx.ftz.f32 %0, %1;" : "=f"(r) : "f"(x));
    return r;
}
__device__ __forceinline__ unsigned redux_min_u32(unsigned v) {
    unsigned d;
    asm("redux.sync.min.u32 %0, %1, 0xffffffff;" : "=r"(d) : "r"(v));
    return d;
}

// ---------------------------------------------------------------------------
// k_combo: grid (3 roles, 64 batches), 256 threads.
//  role 0 (serial chain for batch b):
//    - grid bounds (minx/maxx = both coords of history POINT 0 over all
//      batches; miny/maxy = both coords of POINT 1), linspace grids
//    - S[k] = sum_j Bx[j][kx]*Ay[j][ky] (separable tables, 4 passes of 96 j,
//      175 threads own 4(kx)x1(ky) register tiles, accumulators persist)
//    - 16-step sequential argmin (redux.sync.min two-phase, exact first-index
//      tie-break; argmin(ll)==argmin(S)), preds -> out + smem tab
//    - GMM tail rows 384..399 (the only rows needing preds) -> g_arg[b]
//  roles 1,2: GMM history-triangle halves (rows 1..383, independent of
//    preds; run CONCURRENTLY with role 0) -> g_tri[b][role-1]
//  GMM math: logp_i = log(sum_{j<i} e_j*g_ij) - log(sum_{j<i} e_j) - C,
//  e_j = exp(beta*t_j) (the exp(-beta*t_i) factor cancels).
// ---------------------------------------------------------------------------
__global__ __launch_bounds__(256, 2)
void k_combo(const float* __restrict__ curr,
             const float* __restrict__ itime,
             const float* __restrict__ hist,
             const float* __restrict__ beta_p,
             const float* __restrict__ logsig_p,
             float* __restrict__ out) {
    __shared__ __align__(16) float Bx[JCH * TROW];   // 10752 B
    __shared__ __align__(16) float Ay[JCH * TROW];   // 10752 B
    __shared__ __align__(16) float4 tab[LF];         // (px,py,bt,e) 6400 B
    __shared__ float sxa[JCH], sya[JCH], sbta[JCH];
    __shared__ float Sfull[CAND];                    // 2500 B
    __shared__ float xl[NG], yl[NG];
    __shared__ float bounds[4];
    __shared__ float sct[NPLT];
    __shared__ unsigned wval[2][8], widx[2][8];
    __shared__ float wacc[8];

    const int role = blockIdx.x;   // 0..2
    const int b    = blockIdx.y;
    const int t    = threadIdx.x;  // 256
    const int w    = t >> 5, lane = t & 31;

    const float beta = beta_p[0];
    const float ls   = logsig_p[0];
    const float sig  = __expf(ls);
    const float c2   = (0.5f / (sig * sig)) * LOG2E_F;

    if (role != 0) {
        // ================= triangle halves (roles 1,2) =====================
        // stage tab (history only)
        for (int j = t; j < HH; j += 256) {
            float hx = hist[b * (HH * 2) + 2 * j];
            float hy = hist[b * (HH * 2) + 2 * j + 1];
            float bt = beta * itime[b * HH + j] * LOG2E_F;
            tab[j] = make_float4(hx, hy, bt, ex2f(bt));
        }
        __syncthreads();

        float acc = 0.f;
        // rows i = role, role+2, ... interleaved across 8 warps
        for (int i = role + 2 * w; i < HH; i += 16) {
            if (i == 0) continue;
            float4 pi = tab[i];
            float s1 = 0.f, s2 = 0.f;
            for (int j = lane; j < i; j += 32) {
                float4 pj = tab[j];
                float dx = pi.x - pj.x;
                float dy = pi.y - pj.y;
                float sq = fmaf(dx, dx, dy * dy);
                s1 += pj.w;
                s2 += ex2f(fmaf(-c2, sq, pj.z));
            }
#pragma unroll
            for (int o = 16; o; o >>= 1) {
                s1 += __shfl_down_sync(0xffffffffu, s1, o);
                s2 += __shfl_down_sync(0xffffffffu, s2, o);
            }
            if (lane == 0) acc += __logf(s2) - __logf(s1);
        }
        if (lane == 0) wacc[w] = acc;
        __syncthreads();
        if (t == 0) {
            float tot = 0.f;
#pragma unroll
            for (int q = 0; q < 8; q++) tot += wacc[q];
            g_tri[b][role - 1] = tot;
        }
        return;
    }

    // ======================= role 0: serial chain ==========================
    // ---- bounds: warp w in {0,1} reduces history POINT index w ----
    if (w < 2) {
        float a0 = hist[lane * (HH * 2) + 2 * w + 0];
        float a1 = hist[lane * (HH * 2) + 2 * w + 1];
        float b0 = hist[(lane + 32) * (HH * 2) + 2 * w + 0];
        float b1 = hist[(lane + 32) * (HH * 2) + 2 * w + 1];
        float mn = fminf(fminf(a0, a1), fminf(b0, b1));
        float mx = fmaxf(fmaxf(a0, a1), fmaxf(b0, b1));
#pragma unroll
        for (int o = 16; o; o >>= 1) {
            mn = fminf(mn, __shfl_xor_sync(0xffffffffu, mn, o));
            mx = fmaxf(mx, __shfl_xor_sync(0xffffffffu, mx, o));
        }
        if (lane == 0) { bounds[2 * w] = mn; bounds[2 * w + 1] = mx; }
    }
    if (t >= 64 && t < 64 + NPLT) sct[t - 64] = curr[b * NPLT + (t - 64)];
    // stage tab (history) early — also warms L2 lines for sxa staging
    for (int j = t; j < HH; j += 256) {
        float hx = hist[b * (HH * 2) + 2 * j];
        float hy = hist[b * (HH * 2) + 2 * j + 1];
        float bt = beta * itime[b * HH + j] * LOG2E_F;
        tab[j] = make_float4(hx, hy, bt, ex2f(bt));
    }
    __syncthreads();

    if (t < NG) {
        float minx = bounds[0], maxx = bounds[1];
        float miny = bounds[2], maxy = bounds[3];
        xl[t] = (t == NG - 1) ? maxx : minx + (maxx - minx) * ((float)t / (float)(NG - 1));
        yl[t] = (t == NG - 1) ? maxy : miny + (maxy - miny) * ((float)t / (float)(NG - 1));
    }
    __syncthreads();

    // ---- S phase: 4 passes of 96 j, register-tile GEMM ----
    const int tx = t % 7;   // meaningful for t < 175
    const int ky = t / 7;
    float ac0 = 0.f, ac1 = 0.f, ac2 = 0.f, ac3 = 0.f;

    for (int p = 0; p < NP; p++) {
        // tables for this pass (sources from tab in smem — no LDG)
        for (int e = t; e < JCH * TROW; e += 256) {
            int j = e / TROW, kc = e - j * TROW;
            if (kc < NG) {
                float4 pj = tab[p * JCH + j];
                float dx = xl[kc] - pj.x;
                float dy = yl[kc] - pj.y;
                Bx[e] = ex2f(fmaf(-c2, dx * dx, pj.z));
                Ay[e] = ex2f(-c2 * dy * dy);
            } else {
                Bx[e] = 0.f;
                Ay[e] = 0.f;
            }
        }
        __syncthreads();
        if (t < 175) {
#pragma unroll 4
            for (int j = 0; j < JCH; j++) {
                float4 bx = *(const float4*)&Bx[j * TROW + tx * 4];
                float  ay = Ay[j * TROW + ky];
                ac0 = fmaf(bx.x, ay, ac0);
                ac1 = fmaf(bx.y, ay, ac1);
                ac2 = fmaf(bx.z, ay, ac2);
                ac3 = fmaf(bx.w, ay, ac3);
            }
        }
        __syncthreads();
    }
    if (t < 175) {
        int kx = tx * 4;
        float* dst = &Sfull[ky * NG + kx];
        dst[0] = ac0;
        if (kx + 1 < NG) dst[1] = ac1;
        if (kx + 2 < NG) dst[2] = ac2;
        if (kx + 3 < NG) dst[3] = ac3;
    }
    __syncthreads();

    // ---- 16-step argmin (R9-proven: redux two-phase, parity smem) ----
    const int NR = 3;
    float s[NR], cx[NR], cy[NR];
#pragma unroll
    for (int r = 0; r < NR; r++) {
        int k = t + 256 * r;
        if (k < CAND) {
            s[r]  = Sfull[k];
            cx[r] = xl[k % NG];
            cy[r] = yl[k / NG];
        } else {
            s[r] = __uint_as_float(0xFFFFFFFFu);
            cx[r] = 0.f; cy[r] = 0.f;
        }
    }

    for (int i = 0; i < NPLT; i++) {
        const int p = i & 1;
        unsigned vb = 0xFFFFFFFFu;
#pragma unroll
        for (int r = 0; r < NR; r++) {
            unsigned u = __float_as_uint(s[r]);
            vb = (u < vb) ? u : vb;
        }
        unsigned wv = redux_min_u32(vb);
        if (lane == 0) wval[p][w] = wv;
        __syncthreads();
        unsigned gmin = wval[p][0];
#pragma unroll
        for (int q = 1; q < 8; q++) gmin = (wval[p][q] < gmin) ? wval[p][q] : gmin;

        unsigned ki = 0xFFFFFFFFu;
#pragma unroll
        for (int r = NR - 1; r >= 0; r--) {
            if (__float_as_uint(s[r]) == gmin) ki = (unsigned)(t + 256 * r);
        }
        unsigned wi = redux_min_u32(ki);
        if (lane == 0) widx[p][w] = wi;
        __syncthreads();
        unsigned idx = widx[p][0];
#pragma unroll
        for (int q = 1; q < 8; q++) idx = (widx[p][q] < idx) ? widx[p][q] : idx;

        float px = xl[idx % NG];
        float py = yl[idx / NG];
        float bti = beta * sct[i] * LOG2E_F;
        if (t == 0) {
            out[BB + (i * BB + b) * 2 + 0] = px;
            out[BB + (i * BB + b) * 2 + 1] = py;
            tab[HH + i] = make_float4(px, py, bti, ex2f(bti));
        }
        if (i < NPLT - 1) {
#pragma unroll
            for (int r = 0; r < NR; r++) {
                int k = t + 256 * r;
                if (k < CAND) {
                    float dx = cx[r] - px;
                    float dy = cy[r] - py;
                    s[r] += ex2f(fmaf(-c2, fmaf(dx, dx, dy * dy), bti));
                }
            }
        }
    }
    __syncthreads();  // tab preds visible to all warps

    // ---- tail rows 384..399: warp w does rows 384+w and 392+w ----
    float acc = 0.f;
#pragma unroll
    for (int q = 0; q < 2; q++) {
        int i = HH + w + 8 * q;
        float4 pi = tab[i];
        float s1 = 0.f, s2 = 0.f;
        for (int j = lane; j < i; j += 32) {
            float4 pj = tab[j];
            float dx = pi.x - pj.x;
            float dy = pi.y - pj.y;
            float sq = fmaf(dx, dx, dy * dy);
            s1 += pj.w;
            s2 += ex2f(fmaf(-c2, sq, pj.z));
        }
#pragma unroll
        for (int o = 16; o; o >>= 1) {
            s1 += __shfl_down_sync(0xffffffffu, s1, o);
            s2 += __shfl_down_sync(0xffffffffu, s2, o);
        }
        if (lane == 0) acc += __logf(s2) - __logf(s1);
    }
    if (lane == 0) wacc[w] = acc;
    __syncthreads();

    if (t == 0) {
        float tot = 0.f;
#pragma unroll
        for (int q = 0; q < 8; q++) tot += wacc[q];
        float C = 2.f * ls + LOG2PI_F;
        float4 p0 = tab[0];
        float logp0 = -0.5f * (p0.x * p0.x + p0.y * p0.y) - LOG2PI_F;
        g_arg[b] = logp0 + tot - (float)(LF - 1) * C;
    }
}

// ---------------------------------------------------------------------------
// k_final: out[b] = g_arg[b] + g_tri[b][0] + g_tri[b][1]
// ---------------------------------------------------------------------------
__global__ void k_final(float* __restrict__ out) {
    int t = threadIdx.x;
    if (t < BB) out[t] = g_arg[t] + g_tri[t][0] + g_tri[t][1];
}

// ---------------------------------------------------------------------------
extern "C" void kernel_launch(void* const* d_in, const int* in_sizes, int n_in,
                              void* d_out, int out_size) {
    const float* curr   = (const float*)d_in[0];  // (64,16)
    const float* itime  = (const float*)d_in[1];  // (64,384)
    const float* hist   = (const float*)d_in[2];  // (64,384,2)
    // d_in[3..5] (expected_data, aux_*) are dead inputs
    const float* beta   = (const float*)d_in[6];
    const float* logsig = (const float*)d_in[7];
    float* out = (float*)d_out;  // [64 loglik][16*64*2 predicted]

    k_combo<<<dim3(3, BB), 256>>>(curr, itime, hist, beta, logsig, out);
    k_final<<<1, 64>>>(out);
}

// round 12
// speedup vs baseline: 1.3924x; 1.3924x over previous
#include <cuda_runtime.h>

#define BB   64
#define HH   384
#define NPLT 16
#define NG   25
#define CAND 625   // NG*NG
#define LF   400   // HH + NPLT
#define JS   4     // S j-chunks
#define JCH  96    // j per chunk (4*96 = 384)
#define TROW 28    // padded table row (floats): 7 tiles x 4

#define LOG2E_F  1.4426950408889634f
#define LOG2PI_F 1.8378770664093453f

// persistent scratch (allocation-free rule: __device__ globals; zero-init at
// load, and the consumer resets flags each run to keep the invariant).
__device__ float g_Spart[JS][BB * CAND];
__device__ float g_tri[BB][2];
__device__ int   g_flagS[BB][JS];
__device__ int   g_flagT[BB][2];

__device__ __forceinline__ float ex2f(float x) {
    float r;
    asm("ex2.approx.ftz.f32 %0, %1;" : "=f"(r) : "f"(x));
    return r;
}
__device__ __forceinline__ unsigned redux_min_u32(unsigned v) {
    unsigned d;
    asm("redux.sync.min.u32 %0, %1, 0xffffffff;" : "=r"(d) : "r"(v));
    return d;
}

// ---------------------------------------------------------------------------
// Single kernel, grid 448 x 256 threads, three roles (all blocks co-resident:
// 28KB smem, 256 thr -> <=4 blocks/SM => 448 <= 148*4; consumers have the
// HIGHEST bids so producers are scheduled first; spin cannot deadlock).
//
//  bid in [0,256):   S-partial producer. jc=bid>>6, b=bid&63.
//     S[b][k] = sum_{j in chunk} Bx[j][kx]*Ay[j][ky]  (separable tables,
//     Bx=exp(bt_j - c2*dx^2), Ay=exp(-c2*dy^2); 175 threads own 4x1 tiles)
//     -> g_Spart[jc][b], then __syncthreads + t0 threadfence + flag.
//  bid in [256,384): GMM triangle half. z=(bid-256)>>6, b=(bid-256)&63.
//     rows z+1, z+3, ... (odd/even split of 1..383; prediction-independent)
//     logp_i = log(sum_{j<i} e_j*g_ij) - log(sum_{j<i} e_j) - C per row
//     (e_j = exp(beta*t_j); the exp(-beta*t_i) factor cancels)
//     -> g_tri[b][z], t0 threadfence + flag.
//  bid in [384,448): consumer, b=bid-384.
//     stage tab/grids, spin-acquire 4 S flags, 16-step sequential argmin
//     (redux.sync.min two-phase -> exact first-index tie-break;
//     argmin(ll)==argmin(S)), preds -> out + tab, GMM tail rows 384..399,
//     spin-acquire triangle flags, final out[b], reset all 6 flags.
//
// Grid-bounds semantics (reference nd[:,0]/nd[:,1]):
//   minx/maxx = min/max over BOTH coords of history POINT 0 (all batches)
//   miny/maxy = min/max over BOTH coords of history POINT 1 (all batches)
// ---------------------------------------------------------------------------
__global__ __launch_bounds__(256, 4)
void k_all(const float* __restrict__ curr,
           const float* __restrict__ itime,
           const float* __restrict__ hist,
           const float* __restrict__ beta_p,
           const float* __restrict__ logsig_p,
           float* __restrict__ out) {
    __shared__ __align__(16) float Bx[JCH * TROW];   // 10752 B
    __shared__ __align__(16) float Ay[JCH * TROW];   // 10752 B
    __shared__ __align__(16) float4 tab[LF];         //  6400 B
    __shared__ float sxa[JCH], sya[JCH], sbta[JCH];
    __shared__ float xl[NG], yl[NG];
    __shared__ float bounds[4];
    __shared__ float sct[NPLT];
    __shared__ unsigned wval[2][8], widx[2][8];
    __shared__ float wacc[8];

    const int bid  = blockIdx.x;
    const int t    = threadIdx.x;
    const int w    = t >> 5, lane = t & 31;

    const float beta = beta_p[0];
    const float ls   = logsig_p[0];
    const float sig  = __expf(ls);
    const float c2   = (0.5f / (sig * sig)) * LOG2E_F;

    // =======================================================================
    if (bid < 256) {            // ---------------- S producer ----------------
        const int jc = bid >> 6;
        const int b  = bid & 63;

        if (w < 2) {  // bounds
            float a0 = hist[lane * (HH * 2) + 2 * w + 0];
            float a1 = hist[lane * (HH * 2) + 2 * w + 1];
            float b0 = hist[(lane + 32) * (HH * 2) + 2 * w + 0];
            float b1 = hist[(lane + 32) * (HH * 2) + 2 * w + 1];
            float mn = fminf(fminf(a0, a1), fminf(b0, b1));
            float mx = fmaxf(fmaxf(a0, a1), fmaxf(b0, b1));
#pragma unroll
            for (int o = 16; o; o >>= 1) {
                mn = fminf(mn, __shfl_xor_sync(0xffffffffu, mn, o));
                mx = fmaxf(mx, __shfl_xor_sync(0xffffffffu, mx, o));
            }
            if (lane == 0) { bounds[2 * w] = mn; bounds[2 * w + 1] = mx; }
        }
        if (t >= 64 && t < 64 + JCH) {  // stage chunk (warps 2..4)
            int j = t - 64;
            int jj = jc * JCH + j;
            sxa[j]  = hist[b * (HH * 2) + 2 * jj];
            sya[j]  = hist[b * (HH * 2) + 2 * jj + 1];
            sbta[j] = beta * itime[b * HH + jj] * LOG2E_F;
        }
        __syncthreads();

        if (t < NG) {
            float minx = bounds[0], maxx = bounds[1];
            float miny = bounds[2], maxy = bounds[3];
            xl[t] = (t == NG - 1) ? maxx : minx + (maxx - minx) * ((float)t / (float)(NG - 1));
            yl[t] = (t == NG - 1) ? maxy : miny + (maxy - miny) * ((float)t / (float)(NG - 1));
        }
        __syncthreads();

        for (int e = t; e < JCH * TROW; e += 256) {
            int j = e / TROW, kc = e - j * TROW;
            if (kc < NG) {
                float dx = xl[kc] - sxa[j];
                float dy = yl[kc] - sya[j];
                Bx[e] = ex2f(fmaf(-c2, dx * dx, sbta[j]));
                Ay[e] = ex2f(-c2 * dy * dy);
            } else {
                Bx[e] = 0.f;
                Ay[e] = 0.f;
            }
        }
        __syncthreads();

        if (t < 175) {
            const int tx = t % 7;
            const int ky = t / 7;
            float ac0 = 0.f, ac1 = 0.f, ac2 = 0.f, ac3 = 0.f;
#pragma unroll 4
            for (int j = 0; j < JCH; j++) {
                float4 bx = *(const float4*)&Bx[j * TROW + tx * 4];
                float  ay = Ay[j * TROW + ky];
                ac0 = fmaf(bx.x, ay, ac0);
                ac1 = fmaf(bx.y, ay, ac1);
                ac2 = fmaf(bx.z, ay, ac2);
                ac3 = fmaf(bx.w, ay, ac3);
            }
            int kx = tx * 4;
            float* dst = &g_Spart[jc][b * CAND + ky * NG + kx];
            dst[0] = ac0;
            if (kx + 1 < NG) dst[1] = ac1;
            if (kx + 2 < NG) dst[2] = ac2;
            if (kx + 3 < NG) dst[3] = ac3;
        }
        __syncthreads();
        if (t == 0) {
            __threadfence();                     // release g_Spart writes
            *(volatile int*)&g_flagS[b][jc] = 1;
        }
        return;
    }

    // =======================================================================
    if (bid < 384) {            // --------------- triangle half --------------
        const int z = (bid - 256) >> 6;
        const int b = (bid - 256) & 63;

        for (int j = t; j < HH; j += 256) {
            float hx = hist[b * (HH * 2) + 2 * j];
            float hy = hist[b * (HH * 2) + 2 * j + 1];
            float bt = beta * itime[b * HH + j] * LOG2E_F;
            tab[j] = make_float4(hx, hy, bt, ex2f(bt));
        }
        __syncthreads();

        float acc = 0.f;
        for (int i = (z + 1) + 2 * w; i < HH; i += 16) {
            float4 pi = tab[i];
            float s1 = 0.f, s2 = 0.f;
            for (int j = lane; j < i; j += 32) {
                float4 pj = tab[j];
                float dx = pi.x - pj.x;
                float dy = pi.y - pj.y;
                float sq = fmaf(dx, dx, dy * dy);
                s1 += pj.w;
                s2 += ex2f(fmaf(-c2, sq, pj.z));
            }
#pragma unroll
            for (int o = 16; o; o >>= 1) {
                s1 += __shfl_down_sync(0xffffffffu, s1, o);
                s2 += __shfl_down_sync(0xffffffffu, s2, o);
            }
            if (lane == 0) acc += __logf(s2) - __logf(s1);
        }
        if (lane == 0) wacc[w] = acc;
        __syncthreads();
        if (t == 0) {
            float tot = 0.f;
#pragma unroll
            for (int q = 0; q < 8; q++) tot += wacc[q];
            g_tri[b][z] = tot;
            __threadfence();                     // release
            *(volatile int*)&g_flagT[b][z] = 1;
        }
        return;
    }

    // =======================================================================
    // --------------------------- consumer / argmin -------------------------
    const int b = bid - 384;

    if (w < 2) {  // bounds
        float a0 = hist[lane * (HH * 2) + 2 * w + 0];
        float a1 = hist[lane * (HH * 2) + 2 * w + 1];
        float b0 = hist[(lane + 32) * (HH * 2) + 2 * w + 0];
        float b1 = hist[(lane + 32) * (HH * 2) + 2 * w + 1];
        float mn = fminf(fminf(a0, a1), fminf(b0, b1));
        float mx = fmaxf(fmaxf(a0, a1), fmaxf(b0, b1));
#pragma unroll
        for (int o = 16; o; o >>= 1) {
            mn = fminf(mn, __shfl_xor_sync(0xffffffffu, mn, o));
            mx = fmaxf(mx, __shfl_xor_sync(0xffffffffu, mx, o));
        }
        if (lane == 0) { bounds[2 * w] = mn; bounds[2 * w + 1] = mx; }
    }
    if (t >= 64 && t < 64 + NPLT) sct[t - 64] = curr[b * NPLT + (t - 64)];
    for (int j = t; j < HH; j += 256) {
        float hx = hist[b * (HH * 2) + 2 * j];
        float hy = hist[b * (HH * 2) + 2 * j + 1];
        float bt = beta * itime[b * HH + j] * LOG2E_F;
        tab[j] = make_float4(hx, hy, bt, ex2f(bt));
    }
    __syncthreads();

    if (t < NG) {
        float minx = bounds[0], maxx = bounds[1];
        float miny = bounds[2], maxy = bounds[3];
        xl[t] = (t == NG - 1) ? maxx : minx + (maxx - minx) * ((float)t / (float)(NG - 1));
        yl[t] = (t == NG - 1) ? maxy : miny + (maxy - miny) * ((float)t / (float)(NG - 1));
    }
    // spin-acquire the 4 S-chunk flags (producers were scheduled first)
    if (t == 0) {
#pragma unroll
        for (int jc = 0; jc < JS; jc++) {
            volatile int* f = &g_flagS[b][jc];
            while (*f == 0) { __nanosleep(64); }
        }
        __threadfence();                         // acquire
    }
    __syncthreads();

    const int NR = 3;
    float s[NR], cx[NR], cy[NR];
#pragma unroll
    for (int r = 0; r < NR; r++) {
        int k = t + 256 * r;
        if (k < CAND) {
            s[r]  = g_Spart[0][b * CAND + k] + g_Spart[1][b * CAND + k]
                  + g_Spart[2][b * CAND + k] + g_Spart[3][b * CAND + k];
            cx[r] = xl[k % NG];
            cy[r] = yl[k / NG];
        } else {
            s[r] = __uint_as_float(0xFFFFFFFFu);
            cx[r] = 0.f; cy[r] = 0.f;
        }
    }

    for (int i = 0; i < NPLT; i++) {
        const int p = i & 1;
        unsigned vb = 0xFFFFFFFFu;
#pragma unroll
        for (int r = 0; r < NR; r++) {
            unsigned u = __float_as_uint(s[r]);
            vb = (u < vb) ? u : vb;
        }
        unsigned wv = redux_min_u32(vb);
        if (lane == 0) wval[p][w] = wv;
        __syncthreads();
        unsigned gmin = wval[p][0];
#pragma unroll
        for (int q = 1; q < 8; q++) gmin = (wval[p][q] < gmin) ? wval[p][q] : gmin;

        unsigned ki = 0xFFFFFFFFu;
#pragma unroll
        for (int r = NR - 1; r >= 0; r--) {
            if (__float_as_uint(s[r]) == gmin) ki = (unsigned)(t + 256 * r);
        }
        unsigned wi = redux_min_u32(ki);
        if (lane == 0) widx[p][w] = wi;
        __syncthreads();
        unsigned idx = widx[p][0];
#pragma unroll
        for (int q = 1; q < 8; q++) idx = (widx[p][q] < idx) ? widx[p][q] : idx;

        float px = xl[idx % NG];
        float py = yl[idx / NG];
        float bti = beta * sct[i] * LOG2E_F;
        if (t == 0) {
            out[BB + (i * BB + b) * 2 + 0] = px;
            out[BB + (i * BB + b) * 2 + 1] = py;
            tab[HH + i] = make_float4(px, py, bti, ex2f(bti));
        }
        if (i < NPLT - 1) {
#pragma unroll
            for (int r = 0; r < NR; r++) {
                int k = t + 256 * r;
                if (k < CAND) {
                    float dx = cx[r] - px;
                    float dy = cy[r] - py;
                    s[r] += ex2f(fmaf(-c2, fmaf(dx, dx, dy * dy), bti));
                }
            }
        }
    }
    __syncthreads();  // tab preds visible

    // tail rows 384..399: warp w does rows 384+w and 392+w
    float acc = 0.f;
#pragma unroll
    for (int q = 0; q < 2; q++) {
        int i = HH + w + 8 * q;
        float4 pi = tab[i];
        float s1 = 0.f, s2 = 0.f;
        for (int j = lane; j < i; j += 32) {
            float4 pj = tab[j];
            float dx = pi.x - pj.x;
            float dy = pi.y - pj.y;
            float sq = fmaf(dx, dx, dy * dy);
            s1 += pj.w;
            s2 += ex2f(fmaf(-c2, sq, pj.z));
        }
#pragma unroll
        for (int o = 16; o; o >>= 1) {
            s1 += __shfl_down_sync(0xffffffffu, s1, o);
            s2 += __shfl_down_sync(0xffffffffu, s2, o);
        }
        if (lane == 0) acc += __logf(s2) - __logf(s1);
    }
    if (lane == 0) wacc[w] = acc;
    __syncthreads();

    if (t == 0) {
        float tot = 0.f;
#pragma unroll
        for (int q = 0; q < 8; q++) tot += wacc[q];
        // spin-acquire triangle flags (usually already set)
#pragma unroll
        for (int z = 0; z < 2; z++) {
            volatile int* f = &g_flagT[b][z];
            while (*f == 0) { __nanosleep(64); }
        }
        __threadfence();                         // acquire
        float tri = g_tri[b][0] + g_tri[b][1];
        float C = 2.f * ls + LOG2PI_F;
        float4 p0 = tab[0];
        float logp0 = -0.5f * (p0.x * p0.x + p0.y * p0.y) - LOG2PI_F;
        out[b] = logp0 + tot + tri - (float)(LF - 1) * C;
        // consumer-reset: restore zero-invariant for the next graph replay
#pragma unroll
        for (int jc = 0; jc < JS; jc++) g_flagS[b][jc] = 0;
        g_flagT[b][0] = 0;
        g_flagT[b][1] = 0;
    }
}

// ---------------------------------------------------------------------------
extern "C" void kernel_launch(void* const* d_in, const int* in_sizes, int n_in,
                              void* d_out, int out_size) {
    const float* curr   = (const float*)d_in[0];  // (64,16)
    const float* itime  = (const float*)d_in[1];  // (64,384)
    const float* hist   = (const float*)d_in[2];  // (64,384,2)
    // d_in[3..5] (expected_data, aux_*) are dead inputs
    const float* beta   = (const float*)d_in[6];
    const float* logsig = (const float*)d_in[7];
    float* out = (float*)d_out;  // [64 loglik][16*64*2 predicted]

    k_all<<<448, 256>>>(curr, itime, hist, beta, logsig, out);
}